// round 1
// baseline (speedup 1.0000x reference)
#include <cuda_runtime.h>
#include <math.h>

// Problem dims
#define BB 128
#define SS 1024
#define QMAX 5001          // q ids 0..5000
#define MSLOT 64
#define KDIM 128
#define VDIM 256
#define FDIM 128
#define NT 131072          // BB*SS

// ---------------- scratch (static device arrays: no allocation) -------------
__device__ float g_Wtab[QMAX * MSLOT];          // softmax(qe @ K^T) per q
__device__ float g_bvE[512];                    // b_value @ [W_erase|W_add]
__device__ float g_PP[10000 * 512];             // W_value @ [W_erase|W_add]
__device__ float g_EAtab[QMAX * 4 * 512];       // [q][r][ erase(256) | add(256) ]
__device__ float g_QStab[QMAX * FDIM];          // qe @ W_summary[256:384] + b_summary
__device__ float g_betatab[QMAX * 3];           // qe @ W_beta + b_beta
__device__ float g_qdtab[QMAX];                 // qe @ W_disc[128:256]
__device__ float g_read[(size_t)NT * VDIM];     // per-step memory reads
__device__ float g_summary[(size_t)NT * FDIM];  // tanh summary

// ---------------- helpers ---------------------------------------------------
__device__ __forceinline__ float sigmoidf_(float x) { return 1.0f / (1.0f + expf(-x)); }
__device__ __forceinline__ float softplusf_(float x) {
    return fmaxf(x, 0.0f) + log1pf(expf(-fabsf(x)));
}

// ---------------- K1: w table (softmax over memory keys) --------------------
__global__ void __launch_bounds__(64) wtab_kernel(const float* __restrict__ qe_table,
                                                  const float* __restrict__ key_memory) {
    int q = blockIdx.x;
    int m = threadIdx.x;
    __shared__ float qe[KDIM];
    __shared__ float sh_d[MSLOT];
    __shared__ float sh_e[MSLOT];
    qe[m]      = qe_table[q * KDIM + m];
    qe[m + 64] = qe_table[q * KDIM + 64 + m];
    __syncthreads();
    float d = 0.0f;
    #pragma unroll 8
    for (int k = 0; k < KDIM; k++) d = fmaf(qe[k], key_memory[m * KDIM + k], d);
    sh_d[m] = d;
    __syncthreads();
    float mx = -1e30f;
    #pragma unroll 8
    for (int i = 0; i < MSLOT; i++) mx = fmaxf(mx, sh_d[i]);
    float e = expf(d - mx);
    sh_e[m] = e;
    __syncthreads();
    float sum = 0.0f;
    #pragma unroll 8
    for (int i = 0; i < MSLOT; i++) sum += sh_e[i];
    g_Wtab[q * MSLOT + m] = e / sum;
}

// ---------------- K1b: b_value @ [W_erase | W_add] --------------------------
__global__ void __launch_bounds__(512) bv_kernel(const float* __restrict__ b_value,
                                                 const float* __restrict__ W_erase,
                                                 const float* __restrict__ W_add) {
    int j = threadIdx.x;
    const float* W = (j < 256) ? (W_erase + j) : (W_add + (j - 256));
    float a = 0.0f;
    for (int k = 0; k < 256; k++) a = fmaf(b_value[k], W[k * 256], a);
    g_bvE[j] = a;
}

// ---------------- K2: SGEMM  PP = W_value(10000x256) @ [W_erase|W_add](256x512)
__global__ void __launch_bounds__(256) sgemm_pp_kernel(const float* __restrict__ A,
                                                       const float* __restrict__ We,
                                                       const float* __restrict__ Wa,
                                                       int M) {
    const int K = 256, N = 512;
    __shared__ float As[8][128];
    __shared__ float Bs[8][128];
    int tid = threadIdx.x;
    int row0 = blockIdx.y * 128, col0 = blockIdx.x * 128;
    int aRow = tid >> 1, aK4 = (tid & 1) * 4;
    int bK = tid >> 5, bCol = (tid & 31) * 4;
    int tx = tid & 15, ty = tid >> 4;
    float acc[8][8];
    #pragma unroll
    for (int i = 0; i < 8; i++)
        #pragma unroll
        for (int j = 0; j < 8; j++) acc[i][j] = 0.0f;

    for (int k0 = 0; k0 < K; k0 += 8) {
        float4 av = make_float4(0, 0, 0, 0);
        int ar = row0 + aRow;
        if (ar < M) av = *(const float4*)(A + (size_t)ar * K + k0 + aK4);
        As[aK4 + 0][aRow] = av.x;
        As[aK4 + 1][aRow] = av.y;
        As[aK4 + 2][aRow] = av.z;
        As[aK4 + 3][aRow] = av.w;
        int j = col0 + bCol;
        const float* bp = (j < 256) ? (We + (k0 + bK) * 256 + j)
                                    : (Wa + (k0 + bK) * 256 + (j - 256));
        *(float4*)&Bs[bK][bCol] = *(const float4*)bp;
        __syncthreads();
        #pragma unroll
        for (int kk = 0; kk < 8; kk++) {
            float ra[8], rb[8];
            #pragma unroll
            for (int i = 0; i < 8; i++) ra[i] = As[kk][ty * 8 + i];
            #pragma unroll
            for (int jj = 0; jj < 8; jj++) rb[jj] = Bs[kk][tx * 8 + jj];
            #pragma unroll
            for (int i = 0; i < 8; i++)
                #pragma unroll
                for (int jj = 0; jj < 8; jj++)
                    acc[i][jj] = fmaf(ra[i], rb[jj], acc[i][jj]);
        }
        __syncthreads();
    }
    #pragma unroll
    for (int i = 0; i < 8; i++) {
        int r = row0 + ty * 8 + i;
        if (r < M) {
            float* cp = g_PP + (size_t)r * N + col0 + tx * 8;
            *(float4*)cp       = make_float4(acc[i][0], acc[i][1], acc[i][2], acc[i][3]);
            *(float4*)(cp + 4) = make_float4(acc[i][4], acc[i][5], acc[i][6], acc[i][7]);
        }
    }
}

// ---------------- K3: build erase/add table ----------------------------------
__global__ void __launch_bounds__(256) ea_kernel(const float* __restrict__ b_erase,
                                                 const float* __restrict__ b_add) {
    int idx = blockIdx.x * 256 + threadIdx.x;
    if (idx >= QMAX * 4 * 512) return;
    int v = idx & 511;
    int r = (idx >> 9) & 3;
    int q = idx >> 11;
    float scale = (float)r * (1.0f / 3.0f);
    float p0 = 0.0f, p1 = 0.0f;
    if (q > 0) {
        p0 = g_PP[(size_t)(q - 1) * 512 + v];
        p1 = g_PP[(size_t)(4999 + q) * 512 + v];
    }
    float bias = (v < 256) ? b_erase[v] : b_add[v - 256];
    float x = p0 + g_bvE[v] + bias + scale * p1;
    g_EAtab[idx] = (v < 256) ? sigmoidf_(x) : tanhf(x);
}

// ---------------- K4: per-q projections (QS, betas, disc-part) ---------------
__global__ void __launch_bounds__(128) perq_kernel(const float* __restrict__ qe_table,
                                                   const float* __restrict__ W_summary,
                                                   const float* __restrict__ b_summary,
                                                   const float* __restrict__ W_beta,
                                                   const float* __restrict__ b_beta,
                                                   const float* __restrict__ W_disc) {
    int q = blockIdx.x;
    int f = threadIdx.x;
    __shared__ float qe[KDIM];
    qe[f] = qe_table[q * KDIM + f];
    __syncthreads();
    float acc = b_summary[f];
    #pragma unroll 8
    for (int d = 0; d < KDIM; d++)
        acc = fmaf(qe[d], W_summary[(256 + d) * FDIM + f], acc);
    g_QStab[q * FDIM + f] = acc;
    if (f < 3) {
        float a = b_beta[f];
        for (int d = 0; d < KDIM; d++) a = fmaf(qe[d], W_beta[d * 3 + f], a);
        g_betatab[q * 3 + f] = a;
    } else if (f == 4) {
        float a = 0.0f;
        for (int d = 0; d < KDIM; d++) a = fmaf(qe[d], W_disc[128 + d], a);
        g_qdtab[q] = a;
    }
}

// ---------------- K5: persistent recurrence scan -----------------------------
// 128 CTAs (one per batch row), 512 threads. Mv in registers: thread(tid) owns
// v = tid>>1, m in [half*32, half*32+32), half = tid&1.
__global__ void __launch_bounds__(512) scan_kernel(const int* __restrict__ q_data,
                                                   const int* __restrict__ r_data,
                                                   const float* __restrict__ initMv) {
    const int b = blockIdx.x;
    const int tid = threadIdx.x;
    const int v = tid >> 1;
    const int half = tid & 1;

    __shared__ int q_sh[SS];
    __shared__ int r_sh[SS];
    __shared__ float w_sh[MSLOT];
    __shared__ float ea_sh[512];

    for (int i = tid; i < SS; i += 512) {
        q_sh[i] = q_data[b * SS + i];
        r_sh[i] = r_data[b * SS + i];
    }

    float R[32];
    #pragma unroll
    for (int i = 0; i < 32; i++)
        R[i] = initMv[(half * 32 + i) * VDIM + v];
    __syncthreads();

    // prefetch step 0
    float pw = 0.0f, pea;
    {
        int q = q_sh[0], r = r_sh[0];
        if (tid < MSLOT) pw = g_Wtab[q * MSLOT + tid];
        pea = g_EAtab[(size_t)(q * 4 + r) * 512 + tid];
    }

    size_t out_base = ((size_t)b << 10);
    for (int s = 0; s < SS; s++) {
        if (tid < MSLOT) w_sh[tid] = pw;
        ea_sh[tid] = pea;
        __syncthreads();
        if (s + 1 < SS) {  // prefetch next step (latency hidden by compute)
            int q = q_sh[s + 1], r = r_sh[s + 1];
            if (tid < MSLOT) pw = g_Wtab[q * MSLOT + tid];
            pea = g_EAtab[(size_t)(q * 4 + r) * 512 + tid];
        }
        float e_v = ea_sh[v];
        float a_v = ea_sh[256 + v];
        float acc = 0.0f;
        #pragma unroll
        for (int i = 0; i < 32; i++) {
            float wm = w_sh[(half << 5) + i];
            acc = fmaf(wm, R[i], acc);            // read uses Mv_{t-1}
            float t = fmaf(-e_v, R[i], a_v);      // a - e*Mv
            R[i] = fmaf(wm, t, R[i]);             // Mv += w*(a - e*Mv)
        }
        acc += __shfl_xor_sync(0xffffffffu, acc, 1);
        if (!half) g_read[((out_base + s) << 8) + v] = acc;
        __syncthreads();
    }
}

// ---------------- K6: summary SGEMM (131072x256 @ 256x128), tanh epilogue ----
__global__ void __launch_bounds__(256) sgemm_sum_kernel(const int* __restrict__ q_data,
                                                        const float* __restrict__ W_summary) {
    const int K = 256, N = 128;
    __shared__ float As[8][128];
    __shared__ float Bs[8][128];
    __shared__ int qrow_s[128];
    int tid = threadIdx.x;
    int row0 = blockIdx.y * 128;  // blockIdx.x == 0 (N==128)
    if (tid < 128) qrow_s[tid] = q_data[row0 + tid];
    int aRow = tid >> 1, aK4 = (tid & 1) * 4;
    int bK = tid >> 5, bCol = (tid & 31) * 4;
    int tx = tid & 15, ty = tid >> 4;
    float acc[8][8];
    #pragma unroll
    for (int i = 0; i < 8; i++)
        #pragma unroll
        for (int j = 0; j < 8; j++) acc[i][j] = 0.0f;

    const float* A = g_read;
    for (int k0 = 0; k0 < K; k0 += 8) {
        float4 av = *(const float4*)(A + (size_t)(row0 + aRow) * K + k0 + aK4);
        As[aK4 + 0][aRow] = av.x;
        As[aK4 + 1][aRow] = av.y;
        As[aK4 + 2][aRow] = av.z;
        As[aK4 + 3][aRow] = av.w;
        *(float4*)&Bs[bK][bCol] = *(const float4*)(W_summary + (k0 + bK) * N + bCol);
        __syncthreads();
        #pragma unroll
        for (int kk = 0; kk < 8; kk++) {
            float ra[8], rb[8];
            #pragma unroll
            for (int i = 0; i < 8; i++) ra[i] = As[kk][ty * 8 + i];
            #pragma unroll
            for (int jj = 0; jj < 8; jj++) rb[jj] = Bs[kk][tx * 8 + jj];
            #pragma unroll
            for (int i = 0; i < 8; i++)
                #pragma unroll
                for (int jj = 0; jj < 8; jj++)
                    acc[i][jj] = fmaf(ra[i], rb[jj], acc[i][jj]);
        }
        __syncthreads();
    }
    #pragma unroll
    for (int i = 0; i < 8; i++) {
        int rl = ty * 8 + i;
        int r = row0 + rl;
        int q = qrow_s[rl];
        #pragma unroll
        for (int jj = 0; jj < 8; jj++) {
            int c = tx * 8 + jj;
            g_summary[(size_t)r * N + c] = tanhf(acc[i][jj] + g_QStab[q * FDIM + c]);
        }
    }
}

// ---------------- K7: per-token head (theta/alpha/CORAL) ---------------------
__global__ void __launch_bounds__(128) head_kernel(const int* __restrict__ q_data,
                                                   const float* __restrict__ W_theta,
                                                   const float* __restrict__ b_theta,
                                                   const float* __restrict__ W_disc,
                                                   const float* __restrict__ b_disc,
                                                   const float* __restrict__ W_c1,
                                                   const float* __restrict__ b_c1,
                                                   const float* __restrict__ W_c2,
                                                   const float* __restrict__ b_c2,
                                                   const float* __restrict__ coral_w,
                                                   const float* __restrict__ coral_b,
                                                   float* __restrict__ out) {
    __shared__ float sWc1[5 * 64], sBc1[64], sWc2[64 * 32], sBc2[32], sCw[32];
    __shared__ float sWth[128], sWd[128];
    __shared__ float h1s[4][64];
    int tid = threadIdx.x;
    for (int i = tid; i < 320; i += 128) sWc1[i] = W_c1[i];
    for (int i = tid; i < 2048; i += 128) sWc2[i] = W_c2[i];
    if (tid < 64) sBc1[tid] = b_c1[tid];
    if (tid < 32) { sBc2[tid] = b_c2[tid]; sCw[tid] = coral_w[tid]; }
    sWth[tid] = W_theta[tid];
    sWd[tid] = W_disc[tid];
    __syncthreads();

    int warp = tid >> 5, lane = tid & 31;
    size_t n = (((size_t)blockIdx.x) << 2) + warp;
    const float* srow = g_summary + n * FDIM;
    float s0 = srow[lane], s1 = srow[lane + 32], s2 = srow[lane + 64], s3 = srow[lane + 96];
    float th = s0 * sWth[lane] + s1 * sWth[lane + 32] + s2 * sWth[lane + 64] + s3 * sWth[lane + 96];
    float dp = s0 * sWd[lane] + s1 * sWd[lane + 32] + s2 * sWd[lane + 64] + s3 * sWd[lane + 96];
    #pragma unroll
    for (int o = 16; o; o >>= 1) {
        th += __shfl_xor_sync(0xffffffffu, th, o);
        dp += __shfl_xor_sync(0xffffffffu, dp, o);
    }
    float theta = (th + b_theta[0]) * 3.0f;
    int q = q_data[n];
    float alpha = softplusf_(dp + g_qdtab[q] + b_disc[0]);
    float be0 = g_betatab[q * 3 + 0];
    float be1 = g_betatab[q * 3 + 1];
    float be2 = g_betatab[q * 3 + 2];
    float feat[5] = {theta, alpha, be0, be1, be2};

    float h1a = sBc1[lane], h1b = sBc1[lane + 32];
    #pragma unroll
    for (int i = 0; i < 5; i++) {
        h1a = fmaf(feat[i], sWc1[i * 64 + lane], h1a);
        h1b = fmaf(feat[i], sWc1[i * 64 + lane + 32], h1b);
    }
    h1s[warp][lane] = fmaxf(h1a, 0.0f);
    h1s[warp][lane + 32] = fmaxf(h1b, 0.0f);
    __syncwarp();
    float h2 = sBc2[lane];
    #pragma unroll
    for (int i = 0; i < 64; i++) h2 = fmaf(h1s[warp][i], sWc2[i * 32 + lane], h2);
    h2 = fmaxf(h2, 0.0f);
    float lg = h2 * sCw[lane];
    #pragma unroll
    for (int o = 16; o; o >>= 1) lg += __shfl_xor_sync(0xffffffffu, lg, o);

    if (lane == 0) {
        float l0 = lg + coral_b[0], l1 = lg + coral_b[1], l2 = lg + coral_b[2];
        float c1 = sigmoidf_(l0);
        float c2 = c1 * sigmoidf_(l1);
        float c3 = c2 * sigmoidf_(l2);
        const size_t N = NT;
        out[n] = theta;
        out[N + n * 3 + 0] = be0;
        out[N + n * 3 + 1] = be1;
        out[N + n * 3 + 2] = be2;
        out[4 * N + n] = alpha;
        out[5 * N + n * 4 + 0] = 1.0f - c1;
        out[5 * N + n * 4 + 1] = c1 - c2;
        out[5 * N + n * 4 + 2] = c2 - c3;
        out[5 * N + n * 4 + 3] = c3;
        out[9 * N + n * 3 + 0] = l0;
        out[9 * N + n * 3 + 1] = l1;
        out[9 * N + n * 3 + 2] = l2;
    }
}

// ---------------- launch -----------------------------------------------------
extern "C" void kernel_launch(void* const* d_in, const int* in_sizes, int n_in,
                              void* d_out, int out_size) {
    const int*   q_data   = (const int*)d_in[0];
    const int*   r_data   = (const int*)d_in[1];
    const float* qe_table = (const float*)d_in[2];
    const float* key_mem  = (const float*)d_in[3];
    const float* initMv   = (const float*)d_in[4];
    const float* W_value  = (const float*)d_in[5];
    const float* b_value  = (const float*)d_in[6];
    const float* W_erase  = (const float*)d_in[7];
    const float* b_erase  = (const float*)d_in[8];
    const float* W_add    = (const float*)d_in[9];
    const float* b_add    = (const float*)d_in[10];
    const float* W_summary= (const float*)d_in[11];
    const float* b_summary= (const float*)d_in[12];
    const float* W_theta  = (const float*)d_in[13];
    const float* b_theta  = (const float*)d_in[14];
    const float* W_beta   = (const float*)d_in[15];
    const float* b_beta   = (const float*)d_in[16];
    const float* W_disc   = (const float*)d_in[17];
    const float* b_disc   = (const float*)d_in[18];
    const float* W_c1     = (const float*)d_in[19];
    const float* b_c1     = (const float*)d_in[20];
    const float* W_c2     = (const float*)d_in[21];
    const float* b_c2     = (const float*)d_in[22];
    const float* coral_w  = (const float*)d_in[23];
    const float* coral_b  = (const float*)d_in[24];
    float* out = (float*)d_out;

    wtab_kernel<<<QMAX, 64>>>(qe_table, key_mem);
    bv_kernel<<<1, 512>>>(b_value, W_erase, W_add);
    {
        dim3 g(4, 79);  // N=512/128, M=ceil(10000/128)
        sgemm_pp_kernel<<<g, 256>>>(W_value, W_erase, W_add, 10000);
    }
    {
        int total = QMAX * 4 * 512;
        ea_kernel<<<(total + 255) / 256, 256>>>(b_erase, b_add);
    }
    perq_kernel<<<QMAX, 128>>>(qe_table, W_summary, b_summary, W_beta, b_beta, W_disc);
    scan_kernel<<<BB, 512>>>(q_data, r_data, initMv);
    {
        dim3 g(1, NT / 128);
        sgemm_sum_kernel<<<g, 256>>>(q_data, W_summary);
    }
    head_kernel<<<NT / 4, 128>>>(q_data, W_theta, b_theta, W_disc, b_disc,
                                 W_c1, b_c1, W_c2, b_c2, coral_w, coral_b, out);
}

// round 3
// speedup vs baseline: 1.1717x; 1.1717x over previous
#include <cuda_runtime.h>
#include <math.h>

// Problem dims
#define BB 128
#define SS 1024
#define QMAX 5001          // q ids 0..5000
#define MSLOT 64
#define KDIM 128
#define VDIM 256
#define FDIM 128
#define NT 131072          // BB*SS

typedef unsigned long long ull;

// ---------------- scratch (static device arrays: no allocation) -------------
__device__ float g_Wtab[QMAX * MSLOT];          // softmax(qe @ K^T) per q
__device__ float g_bvE[512];                    // b_value @ [W_erase|W_add]
__device__ float g_PP[10016 * 512];             // W_value @ [W_erase|W_add]
__device__ float g_EAtab[QMAX * 4 * 512];       // [q][r][ erase(256) | add(256) ]
__device__ float g_QStab[QMAX * FDIM];          // qe @ W_summary[256:384] + b_summary
__device__ float g_betatab[QMAX * 3];           // qe @ W_beta + b_beta
__device__ float g_qdtab[QMAX];                 // qe @ W_disc[128:256]
__device__ float g_read[(size_t)NT * VDIM];     // per-step memory reads
__device__ float g_summary[(size_t)NT * FDIM];  // tanh summary

// ---------------- packed f32x2 helpers --------------------------------------
__device__ __forceinline__ ull pack2(float lo, float hi) {
    ull d; asm("mov.b64 %0, {%1, %2};" : "=l"(d) : "f"(lo), "f"(hi)); return d;
}
__device__ __forceinline__ void unpack2(ull v, float& lo, float& hi) {
    asm("mov.b64 {%0, %1}, %2;" : "=f"(lo), "=f"(hi) : "l"(v));
}
__device__ __forceinline__ ull fma2(ull a, ull b, ull c) {
    ull d; asm("fma.rn.f32x2 %0, %1, %2, %3;" : "=l"(d) : "l"(a), "l"(b), "l"(c));
    return d;
}

__device__ __forceinline__ float sigmoidf_(float x) { return 1.0f / (1.0f + expf(-x)); }
__device__ __forceinline__ float softplusf_(float x) {
    return fmaxf(x, 0.0f) + log1pf(expf(-fabsf(x)));
}

// ---------------- K1: w table (softmax over memory keys) --------------------
__global__ void __launch_bounds__(64) wtab_kernel(const float* __restrict__ qe_table,
                                                  const float* __restrict__ key_memory) {
    int q = blockIdx.x;
    int m = threadIdx.x;
    __shared__ float qe[KDIM];
    __shared__ float sh_d[MSLOT];
    __shared__ float sh_e[MSLOT];
    qe[m]      = qe_table[q * KDIM + m];
    qe[m + 64] = qe_table[q * KDIM + 64 + m];
    __syncthreads();
    float d = 0.0f;
    #pragma unroll 8
    for (int k = 0; k < KDIM; k++) d = fmaf(qe[k], key_memory[m * KDIM + k], d);
    sh_d[m] = d;
    __syncthreads();
    float mx = -1e30f;
    #pragma unroll 8
    for (int i = 0; i < MSLOT; i++) mx = fmaxf(mx, sh_d[i]);
    float e = expf(d - mx);
    sh_e[m] = e;
    __syncthreads();
    float sum = 0.0f;
    #pragma unroll 8
    for (int i = 0; i < MSLOT; i++) sum += sh_e[i];
    g_Wtab[q * MSLOT + m] = e / sum;
}

// ---------------- K1b: b_value @ [W_erase | W_add] --------------------------
__global__ void __launch_bounds__(512) bv_kernel(const float* __restrict__ b_value,
                                                 const float* __restrict__ W_erase,
                                                 const float* __restrict__ W_add) {
    int j = threadIdx.x;
    const float* W = (j < 256) ? (W_erase + j) : (W_add + (j - 256));
    float a = 0.0f;
    for (int k = 0; k < 256; k++) a = fmaf(b_value[k], W[k * 256], a);
    g_bvE[j] = a;
}

// ---------------- K2: SGEMM  PP = W_value(10000x256) @ [W_erase|W_add](256x512)
// packed f32x2 inner loop, duplicated-A shared tile
__global__ void __launch_bounds__(256) sgemm_pp_kernel(const float* __restrict__ A,
                                                       const float* __restrict__ We,
                                                       const float* __restrict__ Wa,
                                                       int M) {
    const int K = 256, N = 512;
    __shared__ float As[8][256];   // duplicated: As[k][2r]=As[k][2r+1]=A[r][k]
    __shared__ float Bs[8][128];
    int tid = threadIdx.x;
    int row0 = blockIdx.y * 128, col0 = blockIdx.x * 128;
    int aRow = tid >> 1, aK4 = (tid & 1) * 4;
    int bK = tid >> 5, bCol = (tid & 31) * 4;
    int tx = tid & 15, ty = tid >> 4;
    ull acc2[8][4];
    #pragma unroll
    for (int i = 0; i < 8; i++)
        #pragma unroll
        for (int j = 0; j < 4; j++) acc2[i][j] = 0ull;

    for (int k0 = 0; k0 < K; k0 += 8) {
        float4 av = make_float4(0, 0, 0, 0);
        int ar = row0 + aRow;
        if (ar < M) av = *(const float4*)(A + (size_t)ar * K + k0 + aK4);
        *(float2*)&As[aK4 + 0][2 * aRow] = make_float2(av.x, av.x);
        *(float2*)&As[aK4 + 1][2 * aRow] = make_float2(av.y, av.y);
        *(float2*)&As[aK4 + 2][2 * aRow] = make_float2(av.z, av.z);
        *(float2*)&As[aK4 + 3][2 * aRow] = make_float2(av.w, av.w);
        int j = col0 + bCol;
        const float* bp = (j < 256) ? (We + (k0 + bK) * 256 + j)
                                    : (Wa + (k0 + bK) * 256 + (j - 256));
        *(float4*)&Bs[bK][bCol] = *(const float4*)bp;
        __syncthreads();
        #pragma unroll
        for (int kk = 0; kk < 8; kk++) {
            ull ra[8], rb[4];
            #pragma unroll
            for (int i = 0; i < 8; i++) ra[i] = *(const ull*)&As[kk][2 * (ty * 8 + i)];
            #pragma unroll
            for (int jp = 0; jp < 4; jp++) rb[jp] = *(const ull*)&Bs[kk][jp * 32 + tx * 2];
            #pragma unroll
            for (int i = 0; i < 8; i++)
                #pragma unroll
                for (int jp = 0; jp < 4; jp++)
                    acc2[i][jp] = fma2(ra[i], rb[jp], acc2[i][jp]);
        }
        __syncthreads();
    }
    #pragma unroll
    for (int i = 0; i < 8; i++) {
        int r = row0 + ty * 8 + i;
        if (r < M) {
            #pragma unroll
            for (int jp = 0; jp < 4; jp++) {
                int c = col0 + jp * 32 + tx * 2;
                float lo, hi; unpack2(acc2[i][jp], lo, hi);
                *(float2*)&g_PP[(size_t)r * N + c] = make_float2(lo, hi);
            }
        }
    }
}

// ---------------- K3: build erase/add table ----------------------------------
__global__ void __launch_bounds__(256) ea_kernel(const float* __restrict__ b_erase,
                                                 const float* __restrict__ b_add) {
    int idx = blockIdx.x * 256 + threadIdx.x;
    if (idx >= QMAX * 4 * 512) return;
    int v = idx & 511;
    int r = (idx >> 9) & 3;
    int q = idx >> 11;
    float scale = (float)r * (1.0f / 3.0f);
    float p0 = 0.0f, p1 = 0.0f;
    if (q > 0) {
        p0 = g_PP[(size_t)(q - 1) * 512 + v];
        p1 = g_PP[(size_t)(4999 + q) * 512 + v];
    }
    float bias = (v < 256) ? b_erase[v] : b_add[v - 256];
    float x = p0 + g_bvE[v] + bias + scale * p1;
    g_EAtab[idx] = (v < 256) ? sigmoidf_(x) : tanhf(x);
}

// ---------------- K4: per-q projections (QS, betas, disc-part) ---------------
__global__ void __launch_bounds__(128) perq_kernel(const float* __restrict__ qe_table,
                                                   const float* __restrict__ W_summary,
                                                   const float* __restrict__ b_summary,
                                                   const float* __restrict__ W_beta,
                                                   const float* __restrict__ b_beta,
                                                   const float* __restrict__ W_disc) {
    int q = blockIdx.x;
    int f = threadIdx.x;
    __shared__ float qe[KDIM];
    qe[f] = qe_table[q * KDIM + f];
    __syncthreads();
    float acc = b_summary[f];
    #pragma unroll 8
    for (int d = 0; d < KDIM; d++)
        acc = fmaf(qe[d], W_summary[(256 + d) * FDIM + f], acc);
    g_QStab[q * FDIM + f] = acc;
    if (f < 3) {
        float a = b_beta[f];
        for (int d = 0; d < KDIM; d++) a = fmaf(qe[d], W_beta[d * 3 + f], a);
        g_betatab[q * 3 + f] = a;
    } else if (f == 4) {
        float a = 0.0f;
        for (int d = 0; d < KDIM; d++) a = fmaf(qe[d], W_disc[128 + d], a);
        g_qdtab[q] = a;
    }
}

// ---------------- K5: persistent recurrence scan (barrier-free, f32x2) -------
// 128 CTAs, 512 threads. Thread owns 2 v (v0=2p, v1=2p+1) x 16 m (8 m-pairs),
// p = tid>>2, quarter = tid&3, m in [quarter*16, quarter*16+16).
// Mv in registers packed over m-pairs. w comes pre-paired from g_Wtab.
__device__ __forceinline__ void scan_pref(int q, int r, int quarter, int p,
                                          ull* W, float& e0, float& e1,
                                          float& a0, float& a1) {
    const ulonglong2* wp = (const ulonglong2*)(g_Wtab + q * MSLOT + quarter * 16);
    ulonglong2 t0 = wp[0], t1 = wp[1], t2 = wp[2], t3 = wp[3];
    W[0] = t0.x; W[1] = t0.y; W[2] = t1.x; W[3] = t1.y;
    W[4] = t2.x; W[5] = t2.y; W[6] = t3.x; W[7] = t3.y;
    const float* ea = g_EAtab + (size_t)(q * 4 + r) * 512;
    float2 ee = *(const float2*)(ea + 2 * p);
    float2 aa = *(const float2*)(ea + 256 + 2 * p);
    e0 = ee.x; e1 = ee.y; a0 = aa.x; a1 = aa.y;
}

__device__ __forceinline__ void scan_step(ull* R0, ull* R1, const ull* W,
                                          float e0, float e1, float a0, float a1,
                                          int quarter, float* outp) {
    ull ne0 = pack2(-e0, -e0), ne1 = pack2(-e1, -e1);
    ull a20 = pack2(a0, a0),   a21 = pack2(a1, a1);
    ull acc0 = 0ull, acc1 = 0ull;
    #pragma unroll
    for (int i = 0; i < 8; i++) {
        ull t0 = fma2(ne0, R0[i], a20);
        ull t1 = fma2(ne1, R1[i], a21);
        acc0 = fma2(W[i], R0[i], acc0);
        acc1 = fma2(W[i], R1[i], acc1);
        R0[i] = fma2(W[i], t0, R0[i]);
        R1[i] = fma2(W[i], t1, R1[i]);
    }
    float x0, y0, x1, y1;
    unpack2(acc0, x0, y0);
    unpack2(acc1, x1, y1);
    float rd0 = x0 + y0, rd1 = x1 + y1;
    rd0 += __shfl_xor_sync(0xffffffffu, rd0, 1);
    rd0 += __shfl_xor_sync(0xffffffffu, rd0, 2);
    rd1 += __shfl_xor_sync(0xffffffffu, rd1, 1);
    rd1 += __shfl_xor_sync(0xffffffffu, rd1, 2);
    if (quarter == 0) *(float2*)outp = make_float2(rd0, rd1);
}

__global__ void __launch_bounds__(512) scan_kernel(const int* __restrict__ q_data,
                                                   const int* __restrict__ r_data,
                                                   const float* __restrict__ initMv) {
    const int b = blockIdx.x;
    const int tid = threadIdx.x;
    const int quarter = tid & 3;
    const int p = tid >> 2;

    __shared__ int q_sh[SS];
    __shared__ int r_sh[SS];
    for (int i = tid; i < SS; i += 512) {
        q_sh[i] = q_data[b * SS + i];
        r_sh[i] = r_data[b * SS + i];
    }

    ull R0[8], R1[8];
    #pragma unroll
    for (int i = 0; i < 8; i++) {
        int m = quarter * 16 + 2 * i;
        R0[i] = pack2(initMv[m * VDIM + 2 * p],     initMv[(m + 1) * VDIM + 2 * p]);
        R1[i] = pack2(initMv[m * VDIM + 2 * p + 1], initMv[(m + 1) * VDIM + 2 * p + 1]);
    }
    __syncthreads();

    ull WA[8], WB[8];
    float eA0, eA1, aA0, aA1, eB0, eB1, aB0, aB1;
    scan_pref(q_sh[0], r_sh[0], quarter, p, WA, eA0, eA1, aA0, aA1);

    float* rdbase = g_read + (((size_t)b << 10)) * VDIM + 2 * p;
    for (int s = 0; s < SS; s += 2) {
        scan_pref(q_sh[s + 1], r_sh[s + 1], quarter, p, WB, eB0, eB1, aB0, aB1);
        scan_step(R0, R1, WA, eA0, eA1, aA0, aA1, quarter, rdbase + (size_t)s * VDIM);
        if (s + 2 < SS)
            scan_pref(q_sh[s + 2], r_sh[s + 2], quarter, p, WA, eA0, eA1, aA0, aA1);
        scan_step(R0, R1, WB, eB0, eB1, aB0, aB1, quarter, rdbase + (size_t)(s + 1) * VDIM);
    }
}

// ---------------- K6: summary SGEMM (131072x256 @ 256x128), f32x2, tanh ------
__global__ void __launch_bounds__(256) sgemm_sum_kernel(const int* __restrict__ q_data,
                                                        const float* __restrict__ W_summary) {
    const int K = 256, N = 128;
    __shared__ float As[8][256];   // duplicated
    __shared__ float Bs[8][128];
    __shared__ int qrow_s[128];
    int tid = threadIdx.x;
    int row0 = blockIdx.x * 128;
    if (tid < 128) qrow_s[tid] = q_data[row0 + tid];
    int aRow = tid >> 1, aK4 = (tid & 1) * 4;
    int bK = tid >> 5, bCol = (tid & 31) * 4;
    int tx = tid & 15, ty = tid >> 4;
    ull acc2[8][4];
    #pragma unroll
    for (int i = 0; i < 8; i++)
        #pragma unroll
        for (int j = 0; j < 4; j++) acc2[i][j] = 0ull;

    const float* A = g_read;
    for (int k0 = 0; k0 < K; k0 += 8) {
        float4 av = *(const float4*)(A + (size_t)(row0 + aRow) * K + k0 + aK4);
        *(float2*)&As[aK4 + 0][2 * aRow] = make_float2(av.x, av.x);
        *(float2*)&As[aK4 + 1][2 * aRow] = make_float2(av.y, av.y);
        *(float2*)&As[aK4 + 2][2 * aRow] = make_float2(av.z, av.z);
        *(float2*)&As[aK4 + 3][2 * aRow] = make_float2(av.w, av.w);
        *(float4*)&Bs[bK][bCol] = *(const float4*)(W_summary + (k0 + bK) * N + bCol);
        __syncthreads();
        #pragma unroll
        for (int kk = 0; kk < 8; kk++) {
            ull ra[8], rb[4];
            #pragma unroll
            for (int i = 0; i < 8; i++) ra[i] = *(const ull*)&As[kk][2 * (ty * 8 + i)];
            #pragma unroll
            for (int jp = 0; jp < 4; jp++) rb[jp] = *(const ull*)&Bs[kk][jp * 32 + tx * 2];
            #pragma unroll
            for (int i = 0; i < 8; i++)
                #pragma unroll
                for (int jp = 0; jp < 4; jp++)
                    acc2[i][jp] = fma2(ra[i], rb[jp], acc2[i][jp]);
        }
        __syncthreads();
    }
    #pragma unroll
    for (int i = 0; i < 8; i++) {
        int rl = ty * 8 + i;
        int r = row0 + rl;
        int q = qrow_s[rl];
        const float* qs = g_QStab + q * FDIM;
        #pragma unroll
        for (int jp = 0; jp < 4; jp++) {
            int c = jp * 32 + tx * 2;
            float lo, hi; unpack2(acc2[i][jp], lo, hi);
            *(float2*)&g_summary[(size_t)r * N + c] =
                make_float2(tanhf(lo + qs[c]), tanhf(hi + qs[c + 1]));
        }
    }
}

// ---------------- K7: per-token head (theta/alpha/CORAL), 32 tokens/warp -----
__global__ void __launch_bounds__(256) head_kernel(const int* __restrict__ q_data,
                                                   const float* __restrict__ W_theta,
                                                   const float* __restrict__ b_theta,
                                                   const float* __restrict__ W_disc,
                                                   const float* __restrict__ b_disc,
                                                   const float* __restrict__ W_c1,
                                                   const float* __restrict__ b_c1,
                                                   const float* __restrict__ W_c2,
                                                   const float* __restrict__ b_c2,
                                                   const float* __restrict__ coral_w,
                                                   const float* __restrict__ coral_b,
                                                   float* __restrict__ out) {
    __shared__ float sWc1[5 * 64], sBc1[64], sWc2[64 * 32], sBc2[32], sCw[32];
    __shared__ float sWth[128], sWd[128];
    __shared__ float h1s[8][64];
    int tid = threadIdx.x;
    for (int i = tid; i < 320; i += 256) sWc1[i] = W_c1[i];
    for (int i = tid; i < 2048; i += 256) sWc2[i] = W_c2[i];
    if (tid < 64) sBc1[tid] = b_c1[tid];
    if (tid < 32) { sBc2[tid] = b_c2[tid]; sCw[tid] = coral_w[tid]; }
    if (tid < 128) { sWth[tid] = W_theta[tid]; sWd[tid] = W_disc[tid]; }
    __syncthreads();

    int warp = tid >> 5, lane = tid & 31;
    float bth = b_theta[0], bd = b_disc[0];
    float cb0 = coral_b[0], cb1 = coral_b[1], cb2 = coral_b[2];
    float wth0 = sWth[lane], wth1 = sWth[lane + 32], wth2 = sWth[lane + 64], wth3 = sWth[lane + 96];
    float wd0 = sWd[lane], wd1 = sWd[lane + 32], wd2 = sWd[lane + 64], wd3 = sWd[lane + 96];
    float cw = sCw[lane];

    const int TOK = 32;
    size_t base = ((size_t)blockIdx.x * 8 + warp) * TOK;
    for (int t = 0; t < TOK; t++) {
        size_t n = base + t;
        const float* srow = g_summary + n * FDIM;
        float s0 = srow[lane], s1 = srow[lane + 32], s2 = srow[lane + 64], s3 = srow[lane + 96];
        float th = s0 * wth0 + s1 * wth1 + s2 * wth2 + s3 * wth3;
        float dp = s0 * wd0 + s1 * wd1 + s2 * wd2 + s3 * wd3;
        #pragma unroll
        for (int o = 16; o; o >>= 1) {
            th += __shfl_xor_sync(0xffffffffu, th, o);
            dp += __shfl_xor_sync(0xffffffffu, dp, o);
        }
        float theta = (th + bth) * 3.0f;
        int q = q_data[n];
        float alpha = softplusf_(dp + g_qdtab[q] + bd);
        float be0 = g_betatab[q * 3 + 0];
        float be1 = g_betatab[q * 3 + 1];
        float be2 = g_betatab[q * 3 + 2];
        float feat[5] = {theta, alpha, be0, be1, be2};

        float h1a = sBc1[lane], h1b = sBc1[lane + 32];
        #pragma unroll
        for (int i = 0; i < 5; i++) {
            h1a = fmaf(feat[i], sWc1[i * 64 + lane], h1a);
            h1b = fmaf(feat[i], sWc1[i * 64 + lane + 32], h1b);
        }
        h1s[warp][lane] = fmaxf(h1a, 0.0f);
        h1s[warp][lane + 32] = fmaxf(h1b, 0.0f);
        __syncwarp();
        float h2 = sBc2[lane];
        #pragma unroll
        for (int i = 0; i < 64; i++) h2 = fmaf(h1s[warp][i], sWc2[i * 32 + lane], h2);
        h2 = fmaxf(h2, 0.0f);
        float lg = h2 * cw;
        #pragma unroll
        for (int o = 16; o; o >>= 1) lg += __shfl_xor_sync(0xffffffffu, lg, o);

        if (lane == 0) {
            float l0 = lg + cb0, l1 = lg + cb1, l2 = lg + cb2;
            float c1 = sigmoidf_(l0);
            float c2 = c1 * sigmoidf_(l1);
            float c3 = c2 * sigmoidf_(l2);
            const size_t N = NT;
            out[n] = theta;
            out[N + n * 3 + 0] = be0;
            out[N + n * 3 + 1] = be1;
            out[N + n * 3 + 2] = be2;
            out[4 * N + n] = alpha;
            out[5 * N + n * 4 + 0] = 1.0f - c1;
            out[5 * N + n * 4 + 1] = c1 - c2;
            out[5 * N + n * 4 + 2] = c2 - c3;
            out[5 * N + n * 4 + 3] = c3;
            out[9 * N + n * 3 + 0] = l0;
            out[9 * N + n * 3 + 1] = l1;
            out[9 * N + n * 3 + 2] = l2;
        }
        __syncwarp();
    }
}

// ---------------- launch -----------------------------------------------------
extern "C" void kernel_launch(void* const* d_in, const int* in_sizes, int n_in,
                              void* d_out, int out_size) {
    const int*   q_data   = (const int*)d_in[0];
    const int*   r_data   = (const int*)d_in[1];
    const float* qe_table = (const float*)d_in[2];
    const float* key_mem  = (const float*)d_in[3];
    const float* initMv   = (const float*)d_in[4];
    const float* W_value  = (const float*)d_in[5];
    const float* b_value  = (const float*)d_in[6];
    const float* W_erase  = (const float*)d_in[7];
    const float* b_erase  = (const float*)d_in[8];
    const float* W_add    = (const float*)d_in[9];
    const float* b_add    = (const float*)d_in[10];
    const float* W_summary= (const float*)d_in[11];
    const float* b_summary= (const float*)d_in[12];
    const float* W_theta  = (const float*)d_in[13];
    const float* b_theta  = (const float*)d_in[14];
    const float* W_beta   = (const float*)d_in[15];
    const float* b_beta   = (const float*)d_in[16];
    const float* W_disc   = (const float*)d_in[17];
    const float* b_disc   = (const float*)d_in[18];
    const float* W_c1     = (const float*)d_in[19];
    const float* b_c1     = (const float*)d_in[20];
    const float* W_c2     = (const float*)d_in[21];
    const float* b_c2     = (const float*)d_in[22];
    const float* coral_w  = (const float*)d_in[23];
    const float* coral_b  = (const float*)d_in[24];
    float* out = (float*)d_out;

    wtab_kernel<<<QMAX, 64>>>(qe_table, key_mem);
    bv_kernel<<<1, 512>>>(b_value, W_erase, W_add);
    {
        dim3 g(4, 79);  // N=512/128, M=ceil(10000/128)
        sgemm_pp_kernel<<<g, 256>>>(W_value, W_erase, W_add, 10000);
    }
    {
        int total = QMAX * 4 * 512;
        ea_kernel<<<(total + 255) / 256, 256>>>(b_erase, b_add);
    }
    perq_kernel<<<QMAX, 128>>>(qe_table, W_summary, b_summary, W_beta, b_beta, W_disc);
    scan_kernel<<<BB, 512>>>(q_data, r_data, initMv);
    sgemm_sum_kernel<<<NT / 128, 256>>>(q_data, W_summary);
    head_kernel<<<NT / (8 * 32), 256>>>(q_data, W_theta, b_theta, W_disc, b_disc,
                                        W_c1, b_c1, W_c2, b_c2, coral_w, coral_b, out);
}